// round 16
// baseline (speedup 1.0000x reference)
#include <cuda_runtime.h>
#include <cuda_fp16.h>
#include <math.h>
#include <stdint.h>

// Problem constants
#define N_NODES 50000
#define N_EDGES 800000
#define N_ET    (N_EDGES + N_NODES)
#define FDIM    256
#define F_IN    128
#define NH      4
#define NC      64
#define NB      64
#define NOUT    16
#define NHID    192
#define KP_MAX  FDIM            // 256 (single fp16 GEMM)

// ---------------- scratch ---------------------------------------------------
__device__ __half g_lin [(size_t)N_NODES * FDIM];
__device__ float g_asrc[N_NODES * NH];
__device__ float g_adst[N_NODES * NH];
__device__ float g_gmax[NB * NC];
__device__ float g_gsum[NB * NC];
__device__ float g_gcnt[NB];
__device__ __half g_abf[(size_t)N_NODES * KP_MAX];
__device__ __half g_bbf[3][FDIM * KP_MAX];

__device__ int g_deg[N_NODES];
__device__ int g_rowptr[N_NODES + 1];
__device__ int g_cursor[N_NODES];
__device__ int g_esrc[N_ET];

// ---------------- helpers ---------------------------------------------------
__device__ __forceinline__ uint32_t smem_u32(const void* p) {
    uint32_t a;
    asm("{ .reg .u64 t; cvta.to.shared.u64 t, %1; cvt.u32.u64 %0, t; }" : "=r"(a) : "l"(p));
    return a;
}
__device__ __forceinline__ void cp_async16(uint32_t dst, const void* src, bool pred) {
    int sz = pred ? 16 : 0;
    asm volatile("cp.async.cg.shared.global [%0], [%1], 16, %2;"
                 :: "r"(dst), "l"(src), "r"(sz) : "memory");
}
#define CP_COMMIT() asm volatile("cp.async.commit_group;" ::: "memory")
#define CP_WAIT(n)  asm volatile("cp.async.wait_group %0;" :: "n"(n) : "memory")

#define LDMATRIX_X4(r0, r1, r2, r3, addr) \
    asm volatile("ldmatrix.sync.aligned.m8n8.x4.shared.b16 {%0,%1,%2,%3}, [%4];" \
        : "=r"(r0), "=r"(r1), "=r"(r2), "=r"(r3) : "r"(addr))

#define MMA_F16(c, a, b0, b1) \
    asm volatile("mma.sync.aligned.m16n8k16.row.col.f32.f16.f16.f32 " \
        "{%0,%1,%2,%3}, {%4,%5,%6,%7}, {%8,%9}, {%0,%1,%2,%3};" \
        : "+f"((c)[0]), "+f"((c)[1]), "+f"((c)[2]), "+f"((c)[3]) \
        : "r"((a)[0]), "r"((a)[1]), "r"((a)[2]), "r"((a)[3]), "r"(b0), "r"(b1))

__device__ __forceinline__ float atomicMaxFloat(float* addr, float value) {
    int* ia = (int*)addr;
    int old = *ia;
    while (__int_as_float(old) < value) {
        int assumed = old;
        old = atomicCAS(ia, assumed, __float_as_int(value));
        if (old == assumed) break;
    }
    return __int_as_float(old);
}

// ========================= CSR construction ================================
__global__ void k_zero_deg() {
    int i = blockIdx.x * blockDim.x + threadIdx.x;
    if (i < N_NODES) g_deg[i] = 0;
    if (i < NB * NC) { g_gmax[i] = -INFINITY; g_gsum[i] = 0.f; }
    if (i < NB) g_gcnt[i] = 0.f;
}
__global__ void k_count(const int* __restrict__ dst) {
    int e = blockIdx.x * blockDim.x + threadIdx.x;
    if (e >= N_ET) return;
    int d = (e < N_EDGES) ? dst[e] : (e - N_EDGES);
    atomicAdd(&g_deg[d], 1);
}
__global__ void k_scan() {
    const int T = 1024;
    __shared__ int tmp[T];
    int t = threadIdx.x;
    const int chunk = (N_NODES + T - 1) / T;
    int start = t * chunk;
    int end = start + chunk; if (end > N_NODES) end = N_NODES;
    int sum = 0;
    for (int i = start; i < end; i++) sum += g_deg[i];
    tmp[t] = sum;
    __syncthreads();
    for (int off = 1; off < T; off <<= 1) {
        int v = (t >= off) ? tmp[t - off] : 0;
        __syncthreads();
        tmp[t] += v;
        __syncthreads();
    }
    int run = tmp[t] - sum;
    for (int i = start; i < end; i++) {
        g_rowptr[i] = run;
        g_cursor[i] = run;
        run += g_deg[i];
    }
    if (t == T - 1) g_rowptr[N_NODES] = run;
}
__global__ void k_scatter(const int* __restrict__ src, const int* __restrict__ dst) {
    int e = blockIdx.x * blockDim.x + threadIdx.x;
    if (e >= N_ET) return;
    int s, d;
    if (e < N_EDGES) { s = src[e]; d = dst[e]; }
    else             { s = d = e - N_EDGES; }
    int pos = atomicAdd(&g_cursor[d], 1);
    g_esrc[pos] = s;
}

// ================= fp16 conversion =========================================
__global__ void k_conv_ab0(const float* __restrict__ in, __half* __restrict__ outa,
                           const float* __restrict__ W, __half* __restrict__ outb,
                           int M, int K, int nblk_a) {
    if ((int)blockIdx.x < nblk_a) {
        int K4 = K >> 2;
        int i = blockIdx.x * blockDim.x + threadIdx.x;
        if (i >= M * K4) return;
        int m = i / K4, k4 = (i - m * K4) << 2;
        float4 v = *(const float4*)(in + (size_t)m * K + k4);
        __half2 h01, h23;
        h01.x = __float2half_rn(v.x); h01.y = __float2half_rn(v.y);
        h23.x = __float2half_rn(v.z); h23.y = __float2half_rn(v.w);
        __half2* o = (__half2*)(outa + (size_t)m * K + k4);
        o[0] = h01; o[1] = h23;
    } else {
        int i = (blockIdx.x - nblk_a) * blockDim.x + threadIdx.x;
        if (i >= K * FDIM) return;
        int n = i & (FDIM - 1), k = i >> 8;
        outb[(size_t)n * K + k] = __float2half_rn(W[(size_t)k * FDIM + n]);
    }
}

__global__ void k_conv_b(const float* __restrict__ W, __half* __restrict__ out, int K) {
    int i = blockIdx.x * blockDim.x + threadIdx.x;
    if (i >= K * FDIM) return;
    int n = i & (FDIM - 1), k = i >> 8;
    out[(size_t)n * K + k] = __float2half_rn(W[(size_t)k * FDIM + n]);
}

// ====== HMMA GEMM: BK=32, 3-stage cp.async, 1 sync/stage, fp16 out =========
#define BM 128
#define BN 128
#define BK 32
#define PAD 8
#define LROW (BK + PAD)
#define TILE_BYTES (BM * LROW * 2)
#define STAGE_BYTES (2 * TILE_BYTES)
#define NSTAGE 3
#define ATT_OFF (NSTAGE * STAGE_BYTES)
#define SMEM_GEMM (ATT_OFF + 2 * FDIM * 4)

__global__ void __launch_bounds__(256)
k_gemm_mma(const __half* __restrict__ A, const __half* __restrict__ B,
           __half* __restrict__ C, const float* __restrict__ atts,
           const float* __restrict__ attd, int M, int Kp) {
    extern __shared__ __align__(16) char smem[];
    float* attSs = (float*)(smem + ATT_OFF);
    float* attDs = attSs + FDIM;

    int tid = threadIdx.x;
    int lane = tid & 31, wid = tid >> 5;
    int warpM = wid & 3;
    int warpN = wid >> 2;
    int m0 = blockIdx.y * BM;
    int n0 = blockIdx.x * BN;

    attSs[tid] = atts[tid];
    attDs[tid] = attd[tid];

    float acc[2][8][4];
    #pragma unroll
    for (int i = 0; i < 2; i++)
        #pragma unroll
        for (int j = 0; j < 8; j++)
            #pragma unroll
            for (int q = 0; q < 4; q++) acc[i][j][q] = 0.f;

    int ns = Kp / BK;
    uint32_t sbase = smem_u32(smem);
    int ldrow = tid >> 2;
    int ldc8  = (tid & 3) * 8;

    auto issue_stage = [&](int st, int bufi) {
        int k0 = st * BK;
        uint32_t aB = sbase + bufi * STAGE_BYTES;
        uint32_t bB = aB + TILE_BYTES;
        #pragma unroll
        for (int r = 0; r < 2; r++) {
            int row = ldrow + r * 64;
            int gm = m0 + row;
            cp_async16(aB + (row * LROW + ldc8) * 2,
                       A + (size_t)gm * Kp + k0 + ldc8, gm < M);
            cp_async16(bB + (row * LROW + ldc8) * 2,
                       B + (size_t)(n0 + row) * Kp + k0 + ldc8, true);
        }
    };

    issue_stage(0, 0); CP_COMMIT();
    issue_stage(1, 1); CP_COMMIT();

    for (int s = 0; s < ns; s++) {
        if (s + 1 < ns) { CP_WAIT(1); } else { CP_WAIT(0); }
        __syncthreads();
        if (s + 2 < ns) { issue_stage(s + 2, (s + 2) % NSTAGE); CP_COMMIT(); }

        int bufi = s % NSTAGE;
        uint32_t aB = sbase + bufi * STAGE_BYTES;
        uint32_t bB = aB + TILE_BYTES;
        #pragma unroll
        for (int ks = 0; ks < 2; ks++) {
            uint32_t a[2][4];
            #pragma unroll
            for (int mi = 0; mi < 2; mi++) {
                uint32_t ad = aB + (((warpM * 32 + mi * 16 + (lane & 15)) * LROW)
                                    + ks * 16 + ((lane >> 4) * 8)) * 2;
                LDMATRIX_X4(a[mi][0], a[mi][1], a[mi][2], a[mi][3], ad);
            }
            uint32_t b[4][4];
            #pragma unroll
            for (int ni = 0; ni < 4; ni++) {
                uint32_t bd = bB + (((warpN * 64 + ni * 16 + (lane & 15)) * LROW)
                                    + ks * 16 + ((lane >> 4) * 8)) * 2;
                LDMATRIX_X4(b[ni][0], b[ni][1], b[ni][2], b[ni][3], bd);
            }
            #pragma unroll
            for (int mi = 0; mi < 2; mi++)
                #pragma unroll
                for (int ni = 0; ni < 4; ni++) {
                    MMA_F16(acc[mi][ni * 2],     a[mi], b[ni][0], b[ni][2]);
                    MMA_F16(acc[mi][ni * 2 + 1], a[mi], b[ni][1], b[ni][3]);
                }
        }
    }

    // epilogue: fp16 store + fused attention coefficients (fp32)
    float sp[2][2] = {}, dp[2][2] = {};
    int qrow = lane >> 2;
    int qcol = (lane & 3) * 2;

    #pragma unroll
    for (int mi = 0; mi < 2; mi++) {
        int mA = m0 + warpM * 32 + mi * 16 + qrow;
        int mB2 = mA + 8;
        bool vA = (mA < M), vB = (mB2 < M);
        #pragma unroll
        for (int ni = 0; ni < 8; ni++) {
            int gcol = n0 + warpN * 64 + ni * 8 + qcol;
            float c0 = acc[mi][ni][0], c1 = acc[mi][ni][1];
            float c2 = acc[mi][ni][2], c3 = acc[mi][ni][3];
            float s0 = attSs[gcol], s1 = attSs[gcol + 1];
            float d0 = attDs[gcol], d1 = attDs[gcol + 1];
            sp[mi][0] += c0 * s0 + c1 * s1;
            sp[mi][1] += c2 * s0 + c3 * s1;
            dp[mi][0] += c0 * d0 + c1 * d1;
            dp[mi][1] += c2 * d0 + c3 * d1;
            if (vA) *(__half2*)(C + (size_t)mA * FDIM + gcol) = __floats2half2_rn(c0, c1);
            if (vB) *(__half2*)(C + (size_t)mB2 * FDIM + gcol) = __floats2half2_rn(c2, c3);
        }
    }
    #pragma unroll
    for (int off = 1; off <= 2; off <<= 1) {
        #pragma unroll
        for (int mi = 0; mi < 2; mi++)
            #pragma unroll
            for (int rp = 0; rp < 2; rp++) {
                sp[mi][rp] += __shfl_xor_sync(0xffffffffu, sp[mi][rp], off);
                dp[mi][rp] += __shfl_xor_sync(0xffffffffu, dp[mi][rp], off);
            }
    }
    if ((lane & 3) == 0) {
        int head = blockIdx.x * 2 + warpN;
        #pragma unroll
        for (int mi = 0; mi < 2; mi++)
            #pragma unroll
            for (int rp = 0; rp < 2; rp++) {
                int m = m0 + warpM * 32 + mi * 16 + qrow + rp * 8;
                if (m < M) {
                    g_asrc[m * NH + head] = sp[mi][rp];
                    g_adst[m * NH + head] = dp[mi][rp];
                }
            }
    }
}

// ======= gather aggregation: single pass; mode 1 fuses graph pooling =======
// grid for this kernel is exactly N_NODES/8 blocks (50000/8 = 6250), so no
// early returns -> __syncthreads in the mode-1 path is safe.
__global__ __launch_bounds__(256) void k_agg(const float* __restrict__ bias, int mode,
                                             const int* __restrict__ batch) {
    __shared__ float s_ex[8][32][4];
    __shared__ int   s_src[8][32];
    __shared__ float p_val[8][NC];
    __shared__ int   p_b[8];
    int gw = (blockIdx.x * blockDim.x + threadIdx.x) >> 5;
    int w = threadIdx.x >> 5;
    int lane = threadIdx.x & 31;
    int d = gw;
    int r0 = g_rowptr[d], r1 = g_rowptr[d + 1];
    int hd = lane >> 3;
    int c0 = lane * 8;

    float4 ad4 = ((const float4*)g_adst)[d];
    float adv[4] = {ad4.x, ad4.y, ad4.z, ad4.w};

    float den[4] = {0.f, 0.f, 0.f, 0.f};
    float acc[8] = {};
    for (int cb = r0; cb < r1; cb += 32) {
        int cnt = r1 - cb; if (cnt > 32) cnt = 32;
        float ex[4] = {0.f, 0.f, 0.f, 0.f};
        int s = 0;
        if (lane < cnt) {
            s = g_esrc[cb + lane];
            float4 as4 = ((const float4*)g_asrc)[s];
            float ev[4] = {as4.x + adv[0], as4.y + adv[1], as4.z + adv[2], as4.w + adv[3]};
            #pragma unroll
            for (int h = 0; h < 4; h++) {
                float e = ev[h] > 0.f ? ev[h] : 0.2f * ev[h];
                ex[h] = __expf(e);
                den[h] += ex[h];
            }
        }
        s_src[w][lane] = s;
        #pragma unroll
        for (int h = 0; h < 4; h++) s_ex[w][lane][h] = ex[h];
        __syncwarp();
        #pragma unroll 4
        for (int j = 0; j < cnt; j++) {
            int sj = s_src[w][j];
            float wgt = s_ex[w][j][hd];
            uint4 hv = *(const uint4*)(g_lin + (size_t)sj * FDIM + c0);
            float2 f0 = __half22float2(*(__half2*)&hv.x);
            float2 f1 = __half22float2(*(__half2*)&hv.y);
            float2 f2 = __half22float2(*(__half2*)&hv.z);
            float2 f3 = __half22float2(*(__half2*)&hv.w);
            acc[0] += wgt * f0.x; acc[1] += wgt * f0.y;
            acc[2] += wgt * f1.x; acc[3] += wgt * f1.y;
            acc[4] += wgt * f2.x; acc[5] += wgt * f2.y;
            acc[6] += wgt * f3.x; acc[7] += wgt * f3.y;
        }
        __syncwarp();
    }
    #pragma unroll
    for (int off = 16; off; off >>= 1)
        #pragma unroll
        for (int h = 0; h < 4; h++)
            den[h] += __shfl_xor_sync(0xffffffffu, den[h], off);

    float inv = 1.f / (den[hd] + 1e-16f);
    float4 bb0 = *(const float4*)(bias + c0);
    float4 bb1 = *(const float4*)(bias + c0 + 4);
    float th[8];
    th[0] = tanhf(acc[0] * inv + bb0.x);
    th[1] = tanhf(acc[1] * inv + bb0.y);
    th[2] = tanhf(acc[2] * inv + bb0.z);
    th[3] = tanhf(acc[3] * inv + bb0.w);
    th[4] = tanhf(acc[4] * inv + bb1.x);
    th[5] = tanhf(acc[5] * inv + bb1.y);
    th[6] = tanhf(acc[6] * inv + bb1.z);
    th[7] = tanhf(acc[7] * inv + bb1.w);

    if (mode == 0) {
        __half2 h2[4];
        #pragma unroll
        for (int j = 0; j < 4; j++) {
            h2[j].x = __float2half_rn(th[2 * j]);
            h2[j].y = __float2half_rn(th[2 * j + 1]);
        }
        *(uint4*)(g_abf + (size_t)d * KP_MAX + c0) = *(uint4*)h2;
    } else {
        // head-mean: channel c = 0.25 * sum over heads (lanes 0-7 end up owning it)
        #pragma unroll
        for (int j = 0; j < 8; j++) {
            th[j] += __shfl_xor_sync(0xffffffffu, th[j], 8);
            th[j] += __shfl_xor_sync(0xffffffffu, th[j], 16);
            th[j] *= 0.25f;
        }
        if (lane < 8) {
            #pragma unroll
            for (int j = 0; j < 8; j++) p_val[w][lane * 8 + j] = th[j];
        }
        if (lane == 0) p_b[w] = batch[d];
        __syncthreads();

        int t = threadIdx.x;
        if (t < NC) {
            int b0 = p_b[0];
            bool uni = true;
            #pragma unroll
            for (int q = 1; q < 8; q++) uni &= (p_b[q] == b0);
            if (uni) {
                float mx = p_val[0][t], sm = p_val[0][t];
                #pragma unroll
                for (int q = 1; q < 8; q++) {
                    float v = p_val[q][t];
                    mx = fmaxf(mx, v);
                    sm += v;
                }
                atomicMaxFloat(&g_gmax[b0 * NC + t], mx);
                atomicAdd(&g_gsum[b0 * NC + t], sm);
                if (t == 0) atomicAdd(&g_gcnt[b0], 8.f);
            } else {
                #pragma unroll
                for (int q = 0; q < 8; q++) {
                    float v = p_val[q][t];
                    int b = p_b[q];
                    atomicMaxFloat(&g_gmax[b * NC + t], v);
                    atomicAdd(&g_gsum[b * NC + t], v);
                }
                if (t == 0)
                    #pragma unroll
                    for (int q = 0; q < 8; q++) atomicAdd(&g_gcnt[p_b[q]], 1.f);
            }
        }
    }
}

// -------- output head -------------------------------------------------------
__global__ void k_out(const float* __restrict__ Wout, const float* __restrict__ bout,
                      float* __restrict__ out) {
    __shared__ float hid[NHID];
    int b = blockIdx.x, t = threadIdx.x;
    float v;
    if (t < 64)       v = g_gmax[b * NC + t];
    else if (t < 128) v = g_gsum[b * NC + (t - 64)] / fmaxf(g_gcnt[b], 1.f);
    else              v = g_gsum[b * NC + (t - 128)];
    hid[t] = v;
    out[NB * NOUT + b * NHID + t] = v;
    __syncthreads();
    if (t < NOUT) {
        float s = bout[t];
        #pragma unroll 8
        for (int k = 0; k < NHID; k++) s += hid[k] * Wout[k * NOUT + t];
        out[b * NOUT + t] = s;
    }
}

// ---------------------------------------------------------------------------
extern "C" void kernel_launch(void* const* d_in, const int* in_sizes, int n_in,
                              void* d_out, int out_size) {
    const float* x     = (const float*)d_in[0];
    const int*   ei    = (const int*)d_in[1];
    const int*   batch = (const int*)d_in[2];
    const float* W[3]    = {(const float*)d_in[3],  (const float*)d_in[7],  (const float*)d_in[11]};
    const float* Aslr[3] = {(const float*)d_in[4],  (const float*)d_in[8],  (const float*)d_in[12]};
    const float* Adlr[3] = {(const float*)d_in[5],  (const float*)d_in[9],  (const float*)d_in[13]};
    const float* Blr[3]  = {(const float*)d_in[6],  (const float*)d_in[10], (const float*)d_in[14]};
    const float* Wout  = (const float*)d_in[15];
    const float* bout  = (const float*)d_in[16];
    float* out = (float*)d_out;

    __half *linbuf, *abf, *bbf0;
    cudaGetSymbolAddress((void**)&linbuf, g_lin);
    cudaGetSymbolAddress((void**)&abf, g_abf);
    cudaGetSymbolAddress((void**)&bbf0, g_bbf);
    __half* bbf[3] = {bbf0, bbf0 + FDIM * KP_MAX, bbf0 + 2 * FDIM * KP_MAX};

    static cudaStream_t s2 = nullptr;
    static cudaEvent_t evf = nullptr, evj = nullptr, evj2 = nullptr;
    if (!s2) {
        cudaStreamCreateWithFlags(&s2, cudaStreamNonBlocking);
        cudaEventCreateWithFlags(&evf, cudaEventDisableTiming);
        cudaEventCreateWithFlags(&evj, cudaEventDisableTiming);
        cudaEventCreateWithFlags(&evj2, cudaEventDisableTiming);
        cudaFuncSetAttribute(k_gemm_mma, cudaFuncAttributeMaxDynamicSharedMemorySize,
                             SMEM_GEMM);
    }

    const int* srcp = ei;
    const int* dstp = ei + N_EDGES;

    // ---- fork: CSR build (+pool init) then conv_b L1/L2 on side stream ----
    cudaEventRecord(evf, 0);
    cudaStreamWaitEvent(s2, evf, 0);
    k_zero_deg<<<(N_NODES + 511) / 512, 512, 0, s2>>>();
    k_count<<<(N_ET + 511) / 512, 512, 0, s2>>>(dstp);
    k_scan<<<1, 1024, 0, s2>>>();
    k_scatter<<<(N_ET + 511) / 512, 512, 0, s2>>>(srcp, dstp);
    cudaEventRecord(evj, s2);                 // CSR ready (for agg L0)
    k_conv_b<<<(FDIM * FDIM + 511) / 512, 512, 0, s2>>>(W[1], bbf[1], FDIM);
    k_conv_b<<<(FDIM * FDIM + 511) / 512, 512, 0, s2>>>(W[2], bbf[2], FDIM);
    cudaEventRecord(evj2, s2);                // B' L1/L2 ready (for gemm L1)

    // ---- main stream: fused conversions + layer-0 GEMM overlap the fork ----
    {
        int nblk_a = (N_NODES * (F_IN / 4) + 511) / 512;
        int nblk_b = (F_IN * FDIM + 511) / 512;
        k_conv_ab0<<<nblk_a + nblk_b, 512>>>(x, abf, W[0], bbf[0],
                                             N_NODES, F_IN, nblk_a);
    }

    dim3 grid(FDIM / BN, (N_NODES + BM - 1) / BM);
    k_gemm_mma<<<grid, 256, SMEM_GEMM>>>(abf, bbf[0], linbuf, Aslr[0], Adlr[0],
                                         N_NODES, F_IN);
    cudaStreamWaitEvent(0, evj, 0);           // need CSR before aggregation
    k_agg<<<N_NODES / 8, 256>>>(Blr[0], 0, batch);
    cudaStreamWaitEvent(0, evj2, 0);          // need B' L1/L2 before next GEMMs

    for (int L = 1; L < 3; L++) {
        k_gemm_mma<<<grid, 256, SMEM_GEMM>>>(abf, bbf[L], linbuf, Aslr[L], Adlr[L],
                                             N_NODES, FDIM);
        k_agg<<<N_NODES / 8, 256>>>(Blr[L], (L == 2) ? 1 : 0, batch);
    }

    k_out<<<NB, NHID>>>(Wout, bout, out);
}

// round 17
// speedup vs baseline: 1.0952x; 1.0952x over previous
#include <cuda_runtime.h>
#include <cuda_fp16.h>
#include <math.h>
#include <stdint.h>

// Problem constants
#define N_NODES 50000
#define N_EDGES 800000
#define N_ET    (N_EDGES + N_NODES)
#define FDIM    256
#define F_IN    128
#define NH      4
#define NC      64
#define NB      64
#define NOUT    16
#define NHID    192
#define KP_MAX  FDIM            // 256 (single fp16 GEMM)

// ---------------- scratch ---------------------------------------------------
__device__ __half g_lin [(size_t)N_NODES * FDIM];
__device__ float g_asrc[N_NODES * NH];
__device__ float g_adst[N_NODES * NH];
__device__ float g_node[N_NODES * NC];
__device__ float g_gmax[NB * NC];
__device__ float g_gsum[NB * NC];
__device__ float g_gcnt[NB];
__device__ __half g_abf[(size_t)N_NODES * KP_MAX];
__device__ __half g_bbf[3][FDIM * KP_MAX];

__device__ int g_deg[N_NODES + 64];     // padded so int4 scan reads stay in-bounds
__device__ int g_rowptr[N_NODES + 1];
__device__ int g_cursor[N_NODES];
__device__ int g_esrc[N_ET];

// ---------------- helpers ---------------------------------------------------
__device__ __forceinline__ uint32_t smem_u32(const void* p) {
    uint32_t a;
    asm("{ .reg .u64 t; cvta.to.shared.u64 t, %1; cvt.u32.u64 %0, t; }" : "=r"(a) : "l"(p));
    return a;
}
__device__ __forceinline__ void cp_async16(uint32_t dst, const void* src, bool pred) {
    int sz = pred ? 16 : 0;
    asm volatile("cp.async.cg.shared.global [%0], [%1], 16, %2;"
                 :: "r"(dst), "l"(src), "r"(sz) : "memory");
}
#define CP_COMMIT() asm volatile("cp.async.commit_group;" ::: "memory")
#define CP_WAIT(n)  asm volatile("cp.async.wait_group %0;" :: "n"(n) : "memory")

#define LDMATRIX_X4(r0, r1, r2, r3, addr) \
    asm volatile("ldmatrix.sync.aligned.m8n8.x4.shared.b16 {%0,%1,%2,%3}, [%4];" \
        : "=r"(r0), "=r"(r1), "=r"(r2), "=r"(r3) : "r"(addr))

#define MMA_F16(c, a, b0, b1) \
    asm volatile("mma.sync.aligned.m16n8k16.row.col.f32.f16.f16.f32 " \
        "{%0,%1,%2,%3}, {%4,%5,%6,%7}, {%8,%9}, {%0,%1,%2,%3};" \
        : "+f"((c)[0]), "+f"((c)[1]), "+f"((c)[2]), "+f"((c)[3]) \
        : "r"((a)[0]), "r"((a)[1]), "r"((a)[2]), "r"((a)[3]), "r"(b0), "r"(b1))

__device__ __forceinline__ float atomicMaxFloat(float* addr, float value) {
    int* ia = (int*)addr;
    int old = *ia;
    while (__int_as_float(old) < value) {
        int assumed = old;
        old = atomicCAS(ia, assumed, __float_as_int(value));
        if (old == assumed) break;
    }
    return __int_as_float(old);
}

// ========================= CSR construction ================================
__global__ void k_zero_deg() {
    int i = blockIdx.x * blockDim.x + threadIdx.x;
    if (i < N_NODES + 64) g_deg[i] = 0;
    if (i < NB * NC) { g_gmax[i] = -INFINITY; g_gsum[i] = 0.f; }
    if (i < NB) g_gcnt[i] = 0.f;
}
__global__ void k_count(const int* __restrict__ dst) {
    int e = blockIdx.x * blockDim.x + threadIdx.x;
    if (e >= N_ET) return;
    int d = (e < N_EDGES) ? dst[e] : (e - N_EDGES);
    atomicAdd(&g_deg[d], 1);
}
// single-block exclusive scan; int4 loads for the per-thread sum phase
__global__ void k_scan() {
    const int T = 1024;
    const int CH = 52;                       // 52*4B = 208B, 16B-aligned chunks
    __shared__ int tmp[T];
    int t = threadIdx.x;
    int start = t * CH;
    int sum = 0;
    if (start < N_NODES + 64) {
        const int4* p4 = (const int4*)(g_deg + start);
        #pragma unroll
        for (int q = 0; q < CH / 4; q++) {
            int4 v = p4[q];
            sum += v.x + v.y + v.z + v.w;    // padding region is zeroed
        }
    }
    tmp[t] = sum;
    __syncthreads();
    for (int off = 1; off < T; off <<= 1) {
        int v = (t >= off) ? tmp[t - off] : 0;
        __syncthreads();
        tmp[t] += v;
        __syncthreads();
    }
    int run = tmp[t] - sum;
    int end = start + CH; if (end > N_NODES) end = N_NODES;
    for (int i = start; i < end; i++) {
        g_rowptr[i] = run;
        g_cursor[i] = run;
        run += g_deg[i];
    }
    if (t == T - 1) g_rowptr[N_NODES] = run;
}
__global__ void k_scatter(const int* __restrict__ src, const int* __restrict__ dst) {
    int e = blockIdx.x * blockDim.x + threadIdx.x;
    if (e >= N_ET) return;
    int s, d;
    if (e < N_EDGES) { s = src[e]; d = dst[e]; }
    else             { s = d = e - N_EDGES; }
    int pos = atomicAdd(&g_cursor[d], 1);
    g_esrc[pos] = s;
}

// ================= fp16 conversion =========================================
__global__ void k_conv_ab0(const float* __restrict__ in, __half* __restrict__ outa,
                           const float* __restrict__ W, __half* __restrict__ outb,
                           int M, int K, int nblk_a) {
    if ((int)blockIdx.x < nblk_a) {
        int K4 = K >> 2;
        int i = blockIdx.x * blockDim.x + threadIdx.x;
        if (i >= M * K4) return;
        int m = i / K4, k4 = (i - m * K4) << 2;
        float4 v = *(const float4*)(in + (size_t)m * K + k4);
        __half2 h01, h23;
        h01.x = __float2half_rn(v.x); h01.y = __float2half_rn(v.y);
        h23.x = __float2half_rn(v.z); h23.y = __float2half_rn(v.w);
        __half2* o = (__half2*)(outa + (size_t)m * K + k4);
        o[0] = h01; o[1] = h23;
    } else {
        int i = (blockIdx.x - nblk_a) * blockDim.x + threadIdx.x;
        if (i >= K * FDIM) return;
        int n = i & (FDIM - 1), k = i >> 8;
        outb[(size_t)n * K + k] = __float2half_rn(W[(size_t)k * FDIM + n]);
    }
}

__global__ void k_conv_b(const float* __restrict__ W, __half* __restrict__ out, int K) {
    int i = blockIdx.x * blockDim.x + threadIdx.x;
    if (i >= K * FDIM) return;
    int n = i & (FDIM - 1), k = i >> 8;
    out[(size_t)n * K + k] = __float2half_rn(W[(size_t)k * FDIM + n]);
}

// ====== HMMA GEMM: BK=32, 3-stage cp.async, 1 sync/stage, fp16 out =========
#define BM 128
#define BN 128
#define BK 32
#define PAD 8
#define LROW (BK + PAD)
#define TILE_BYTES (BM * LROW * 2)
#define STAGE_BYTES (2 * TILE_BYTES)
#define NSTAGE 3
#define ATT_OFF (NSTAGE * STAGE_BYTES)
#define SMEM_GEMM (ATT_OFF + 2 * FDIM * 4)

__global__ void __launch_bounds__(256)
k_gemm_mma(const __half* __restrict__ A, const __half* __restrict__ B,
           __half* __restrict__ C, const float* __restrict__ atts,
           const float* __restrict__ attd, int M, int Kp) {
    extern __shared__ __align__(16) char smem[];
    float* attSs = (float*)(smem + ATT_OFF);
    float* attDs = attSs + FDIM;

    int tid = threadIdx.x;
    int lane = tid & 31, wid = tid >> 5;
    int warpM = wid & 3;
    int warpN = wid >> 2;
    int m0 = blockIdx.y * BM;
    int n0 = blockIdx.x * BN;

    attSs[tid] = atts[tid];
    attDs[tid] = attd[tid];

    float acc[2][8][4];
    #pragma unroll
    for (int i = 0; i < 2; i++)
        #pragma unroll
        for (int j = 0; j < 8; j++)
            #pragma unroll
            for (int q = 0; q < 4; q++) acc[i][j][q] = 0.f;

    int ns = Kp / BK;
    uint32_t sbase = smem_u32(smem);
    int ldrow = tid >> 2;
    int ldc8  = (tid & 3) * 8;

    auto issue_stage = [&](int st, int bufi) {
        int k0 = st * BK;
        uint32_t aB = sbase + bufi * STAGE_BYTES;
        uint32_t bB = aB + TILE_BYTES;
        #pragma unroll
        for (int r = 0; r < 2; r++) {
            int row = ldrow + r * 64;
            int gm = m0 + row;
            cp_async16(aB + (row * LROW + ldc8) * 2,
                       A + (size_t)gm * Kp + k0 + ldc8, gm < M);
            cp_async16(bB + (row * LROW + ldc8) * 2,
                       B + (size_t)(n0 + row) * Kp + k0 + ldc8, true);
        }
    };

    issue_stage(0, 0); CP_COMMIT();
    issue_stage(1, 1); CP_COMMIT();

    for (int s = 0; s < ns; s++) {
        if (s + 1 < ns) { CP_WAIT(1); } else { CP_WAIT(0); }
        __syncthreads();
        if (s + 2 < ns) { issue_stage(s + 2, (s + 2) % NSTAGE); CP_COMMIT(); }

        int bufi = s % NSTAGE;
        uint32_t aB = sbase + bufi * STAGE_BYTES;
        uint32_t bB = aB + TILE_BYTES;
        #pragma unroll
        for (int ks = 0; ks < 2; ks++) {
            uint32_t a[2][4];
            #pragma unroll
            for (int mi = 0; mi < 2; mi++) {
                uint32_t ad = aB + (((warpM * 32 + mi * 16 + (lane & 15)) * LROW)
                                    + ks * 16 + ((lane >> 4) * 8)) * 2;
                LDMATRIX_X4(a[mi][0], a[mi][1], a[mi][2], a[mi][3], ad);
            }
            uint32_t b[4][4];
            #pragma unroll
            for (int ni = 0; ni < 4; ni++) {
                uint32_t bd = bB + (((warpN * 64 + ni * 16 + (lane & 15)) * LROW)
                                    + ks * 16 + ((lane >> 4) * 8)) * 2;
                LDMATRIX_X4(b[ni][0], b[ni][1], b[ni][2], b[ni][3], bd);
            }
            #pragma unroll
            for (int mi = 0; mi < 2; mi++)
                #pragma unroll
                for (int ni = 0; ni < 4; ni++) {
                    MMA_F16(acc[mi][ni * 2],     a[mi], b[ni][0], b[ni][2]);
                    MMA_F16(acc[mi][ni * 2 + 1], a[mi], b[ni][1], b[ni][3]);
                }
        }
    }

    // epilogue: fp16 store + fused attention coefficients (fp32)
    float sp[2][2] = {}, dp[2][2] = {};
    int qrow = lane >> 2;
    int qcol = (lane & 3) * 2;

    #pragma unroll
    for (int mi = 0; mi < 2; mi++) {
        int mA = m0 + warpM * 32 + mi * 16 + qrow;
        int mB2 = mA + 8;
        bool vA = (mA < M), vB = (mB2 < M);
        #pragma unroll
        for (int ni = 0; ni < 8; ni++) {
            int gcol = n0 + warpN * 64 + ni * 8 + qcol;
            float c0 = acc[mi][ni][0], c1 = acc[mi][ni][1];
            float c2 = acc[mi][ni][2], c3 = acc[mi][ni][3];
            float s0 = attSs[gcol], s1 = attSs[gcol + 1];
            float d0 = attDs[gcol], d1 = attDs[gcol + 1];
            sp[mi][0] += c0 * s0 + c1 * s1;
            sp[mi][1] += c2 * s0 + c3 * s1;
            dp[mi][0] += c0 * d0 + c1 * d1;
            dp[mi][1] += c2 * d0 + c3 * d1;
            if (vA) *(__half2*)(C + (size_t)mA * FDIM + gcol) = __floats2half2_rn(c0, c1);
            if (vB) *(__half2*)(C + (size_t)mB2 * FDIM + gcol) = __floats2half2_rn(c2, c3);
        }
    }
    #pragma unroll
    for (int off = 1; off <= 2; off <<= 1) {
        #pragma unroll
        for (int mi = 0; mi < 2; mi++)
            #pragma unroll
            for (int rp = 0; rp < 2; rp++) {
                sp[mi][rp] += __shfl_xor_sync(0xffffffffu, sp[mi][rp], off);
                dp[mi][rp] += __shfl_xor_sync(0xffffffffu, dp[mi][rp], off);
            }
    }
    if ((lane & 3) == 0) {
        int head = blockIdx.x * 2 + warpN;
        #pragma unroll
        for (int mi = 0; mi < 2; mi++)
            #pragma unroll
            for (int rp = 0; rp < 2; rp++) {
                int m = m0 + warpM * 32 + mi * 16 + qrow + rp * 8;
                if (m < M) {
                    g_asrc[m * NH + head] = sp[mi][rp];
                    g_adst[m * NH + head] = dp[mi][rp];
                }
            }
    }
}

// ======= gather aggregation: single pass (R13/R15-proven) ===================
__global__ __launch_bounds__(256) void k_agg(const float* __restrict__ bias, int mode) {
    __shared__ float s_ex[8][32][4];
    __shared__ int   s_src[8][32];
    int gw = (blockIdx.x * blockDim.x + threadIdx.x) >> 5;
    int w = threadIdx.x >> 5;
    int lane = threadIdx.x & 31;
    if (gw >= N_NODES) return;
    int d = gw;
    int r0 = g_rowptr[d], r1 = g_rowptr[d + 1];
    int hd = lane >> 3;
    int c0 = lane * 8;

    float4 ad4 = ((const float4*)g_adst)[d];
    float adv[4] = {ad4.x, ad4.y, ad4.z, ad4.w};

    float den[4] = {0.f, 0.f, 0.f, 0.f};
    float acc[8] = {};
    for (int cb = r0; cb < r1; cb += 32) {
        int cnt = r1 - cb; if (cnt > 32) cnt = 32;
        float ex[4] = {0.f, 0.f, 0.f, 0.f};
        int s = 0;
        if (lane < cnt) {
            s = g_esrc[cb + lane];
            float4 as4 = ((const float4*)g_asrc)[s];
            float ev[4] = {as4.x + adv[0], as4.y + adv[1], as4.z + adv[2], as4.w + adv[3]};
            #pragma unroll
            for (int h = 0; h < 4; h++) {
                float e = ev[h] > 0.f ? ev[h] : 0.2f * ev[h];
                ex[h] = __expf(e);
                den[h] += ex[h];
            }
        }
        s_src[w][lane] = s;
        #pragma unroll
        for (int h = 0; h < 4; h++) s_ex[w][lane][h] = ex[h];
        __syncwarp();
        #pragma unroll 4
        for (int j = 0; j < cnt; j++) {
            int sj = s_src[w][j];
            float wgt = s_ex[w][j][hd];
            uint4 hv = *(const uint4*)(g_lin + (size_t)sj * FDIM + c0);
            float2 f0 = __half22float2(*(__half2*)&hv.x);
            float2 f1 = __half22float2(*(__half2*)&hv.y);
            float2 f2 = __half22float2(*(__half2*)&hv.z);
            float2 f3 = __half22float2(*(__half2*)&hv.w);
            acc[0] += wgt * f0.x; acc[1] += wgt * f0.y;
            acc[2] += wgt * f1.x; acc[3] += wgt * f1.y;
            acc[4] += wgt * f2.x; acc[5] += wgt * f2.y;
            acc[6] += wgt * f3.x; acc[7] += wgt * f3.y;
        }
        __syncwarp();
    }
    #pragma unroll
    for (int off = 16; off; off >>= 1)
        #pragma unroll
        for (int h = 0; h < 4; h++)
            den[h] += __shfl_xor_sync(0xffffffffu, den[h], off);

    float inv = 1.f / (den[hd] + 1e-16f);
    float4 bb0 = *(const float4*)(bias + c0);
    float4 bb1 = *(const float4*)(bias + c0 + 4);
    float th[8];
    th[0] = tanhf(acc[0] * inv + bb0.x);
    th[1] = tanhf(acc[1] * inv + bb0.y);
    th[2] = tanhf(acc[2] * inv + bb0.z);
    th[3] = tanhf(acc[3] * inv + bb0.w);
    th[4] = tanhf(acc[4] * inv + bb1.x);
    th[5] = tanhf(acc[5] * inv + bb1.y);
    th[6] = tanhf(acc[6] * inv + bb1.z);
    th[7] = tanhf(acc[7] * inv + bb1.w);

    if (mode == 0) {
        __half2 h2[4];
        #pragma unroll
        for (int j = 0; j < 4; j++) {
            h2[j].x = __float2half_rn(th[2 * j]);
            h2[j].y = __float2half_rn(th[2 * j + 1]);
        }
        *(uint4*)(g_abf + (size_t)d * KP_MAX + c0) = *(uint4*)h2;
    } else {
        #pragma unroll
        for (int j = 0; j < 8; j++) {
            th[j] += __shfl_xor_sync(0xffffffffu, th[j], 8);
            th[j] += __shfl_xor_sync(0xffffffffu, th[j], 16);
            th[j] *= 0.25f;
        }
        if (lane < 8) {
            float* np = g_node + (size_t)d * NC + lane * 8;
            *(float4*)(np)     = make_float4(th[0], th[1], th[2], th[3]);
            *(float4*)(np + 4) = make_float4(th[4], th[5], th[6], th[7]);
        }
    }
}

// -------- pooling (sorted-batch fast path) ----------------------------------
#define PNODES 64
__global__ __launch_bounds__(256) void k_pool(const int* __restrict__ batch) {
    __shared__ float smax[4][NC], ssum[4][NC];
    int n0 = blockIdx.x * PNODES;
    int nodes = N_NODES - n0; if (nodes > PNODES) nodes = PNODES;
    int c = threadIdx.x & 63, g = threadIdx.x >> 6;

    float mx = -INFINITY, sm = 0.f;
    for (int j = g; j < nodes; j += 4) {
        float v = g_node[(size_t)(n0 + j) * NC + c];
        mx = fmaxf(mx, v);
        sm += v;
    }
    smax[g][c] = mx; ssum[g][c] = sm;
    __syncthreads();

    int b0 = batch[n0], b1 = batch[n0 + nodes - 1];
    if (b0 == b1) {
        if (threadIdx.x < NC) {
            float M = fmaxf(fmaxf(smax[0][c], smax[1][c]), fmaxf(smax[2][c], smax[3][c]));
            float S = ssum[0][c] + ssum[1][c] + ssum[2][c] + ssum[3][c];
            atomicMaxFloat(&g_gmax[b0 * NC + c], M);
            atomicAdd(&g_gsum[b0 * NC + c], S);
        }
        if (threadIdx.x == 0) atomicAdd(&g_gcnt[b0], (float)nodes);
    } else {
        if (threadIdx.x < NC) {
            for (int j = 0; j < nodes; j++) {
                float v = g_node[(size_t)(n0 + j) * NC + c];
                int b = batch[n0 + j];
                atomicMaxFloat(&g_gmax[b * NC + c], v);
                atomicAdd(&g_gsum[b * NC + c], v);
            }
        }
        if (threadIdx.x == 0)
            for (int j = 0; j < nodes; j++) atomicAdd(&g_gcnt[batch[n0 + j]], 1.f);
    }
}
__global__ void k_out(const float* __restrict__ Wout, const float* __restrict__ bout,
                      float* __restrict__ out) {
    __shared__ float hid[NHID];
    int b = blockIdx.x, t = threadIdx.x;
    float v;
    if (t < 64)       v = g_gmax[b * NC + t];
    else if (t < 128) v = g_gsum[b * NC + (t - 64)] / fmaxf(g_gcnt[b], 1.f);
    else              v = g_gsum[b * NC + (t - 128)];
    hid[t] = v;
    out[NB * NOUT + b * NHID + t] = v;
    __syncthreads();
    if (t < NOUT) {
        float s = bout[t];
        #pragma unroll 8
        for (int k = 0; k < NHID; k++) s += hid[k] * Wout[k * NOUT + t];
        out[b * NOUT + t] = s;
    }
}

// ---------------------------------------------------------------------------
extern "C" void kernel_launch(void* const* d_in, const int* in_sizes, int n_in,
                              void* d_out, int out_size) {
    const float* x     = (const float*)d_in[0];
    const int*   ei    = (const int*)d_in[1];
    const int*   batch = (const int*)d_in[2];
    const float* W[3]    = {(const float*)d_in[3],  (const float*)d_in[7],  (const float*)d_in[11]};
    const float* Aslr[3] = {(const float*)d_in[4],  (const float*)d_in[8],  (const float*)d_in[12]};
    const float* Adlr[3] = {(const float*)d_in[5],  (const float*)d_in[9],  (const float*)d_in[13]};
    const float* Blr[3]  = {(const float*)d_in[6],  (const float*)d_in[10], (const float*)d_in[14]};
    const float* Wout  = (const float*)d_in[15];
    const float* bout  = (const float*)d_in[16];
    float* out = (float*)d_out;

    __half *linbuf, *abf, *bbf0;
    cudaGetSymbolAddress((void**)&linbuf, g_lin);
    cudaGetSymbolAddress((void**)&abf, g_abf);
    cudaGetSymbolAddress((void**)&bbf0, g_bbf);
    __half* bbf[3] = {bbf0, bbf0 + FDIM * KP_MAX, bbf0 + 2 * FDIM * KP_MAX};

    static cudaStream_t s2 = nullptr;
    static cudaEvent_t evf = nullptr, evj = nullptr, evj2 = nullptr;
    if (!s2) {
        cudaStreamCreateWithFlags(&s2, cudaStreamNonBlocking);
        cudaEventCreateWithFlags(&evf, cudaEventDisableTiming);
        cudaEventCreateWithFlags(&evj, cudaEventDisableTiming);
        cudaEventCreateWithFlags(&evj2, cudaEventDisableTiming);
        cudaFuncSetAttribute(k_gemm_mma, cudaFuncAttributeMaxDynamicSharedMemorySize,
                             SMEM_GEMM);
    }

    const int* srcp = ei;
    const int* dstp = ei + N_EDGES;

    // ---- fork: CSR build (+pool init) then conv_b L1/L2 on side stream ----
    cudaEventRecord(evf, 0);
    cudaStreamWaitEvent(s2, evf, 0);
    k_zero_deg<<<(N_NODES + 64 + 511) / 512, 512, 0, s2>>>();
    k_count<<<(N_ET + 511) / 512, 512, 0, s2>>>(dstp);
    k_scan<<<1, 1024, 0, s2>>>();
    k_scatter<<<(N_ET + 511) / 512, 512, 0, s2>>>(srcp, dstp);
    cudaEventRecord(evj, s2);                 // CSR ready (for agg L0)
    k_conv_b<<<(FDIM * FDIM + 511) / 512, 512, 0, s2>>>(W[1], bbf[1], FDIM);
    k_conv_b<<<(FDIM * FDIM + 511) / 512, 512, 0, s2>>>(W[2], bbf[2], FDIM);
    cudaEventRecord(evj2, s2);                // B' L1/L2 ready (for gemm L1)

    // ---- main stream: fused conversions + layer-0 GEMM overlap the fork ----
    {
        int nblk_a = (N_NODES * (F_IN / 4) + 511) / 512;
        int nblk_b = (F_IN * FDIM + 511) / 512;
        k_conv_ab0<<<nblk_a + nblk_b, 512>>>(x, abf, W[0], bbf[0],
                                             N_NODES, F_IN, nblk_a);
    }

    dim3 grid(FDIM / BN, (N_NODES + BM - 1) / BM);
    k_gemm_mma<<<grid, 256, SMEM_GEMM>>>(abf, bbf[0], linbuf, Aslr[0], Adlr[0],
                                         N_NODES, F_IN);
    cudaStreamWaitEvent(0, evj, 0);           // need CSR before aggregation
    k_agg<<<(N_NODES * 32 + 255) / 256, 256>>>(Blr[0], 0);
    cudaStreamWaitEvent(0, evj2, 0);          // need B' L1/L2 before next GEMMs

    for (int L = 1; L < 3; L++) {
        k_gemm_mma<<<grid, 256, SMEM_GEMM>>>(abf, bbf[L], linbuf, Aslr[L], Adlr[L],
                                             N_NODES, FDIM);
        k_agg<<<(N_NODES * 32 + 255) / 256, 256>>>(Blr[L], (L == 2) ? 1 : 0);
    }

    k_pool<<<(N_NODES + PNODES - 1) / PNODES, 256>>>(batch);
    k_out<<<NB, NHID>>>(Wout, bout, out);
}